// round 9
// baseline (speedup 1.0000x reference)
#include <cuda_runtime.h>
#include <cuda_bf16.h>
#include <mma.h>
#include <cstdint>

using namespace nvcuda;

#define BB 1024
#define CC 1000
#define HH 512
#define NEG_INF (__int_as_float(0xff800000))

// ---------------- scratch (__device__ globals; zero-initialized) ----------------
__device__ __nv_bfloat16 g_whi[1024 * 512];   // rows >= 1000 stay zero
__device__ __nv_bfloat16 g_wlo[1024 * 512];
__device__ float g_G[1024 * 1024];
__device__ float g_norm[1024];                // diagonal of G (bf16-split accurate)
__device__ float g_ymax[BB];
__device__ int   g_jmax[BB];

// ---------------- cp.async helpers (sm_80+ ISA, base-target safe) ----------------
__device__ __forceinline__ uint32_t smem_u32(const void* p) {
    return (uint32_t)__cvta_generic_to_shared(p);
}
__device__ __forceinline__ void cp16(uint32_t dst, const void* src) {
    asm volatile("cp.async.cg.shared.global [%0], [%1], 16;" :: "r"(dst), "l"(src));
}
__device__ __forceinline__ void cp_commit() {
    asm volatile("cp.async.commit_group;" ::: "memory");
}
template <int N>
__device__ __forceinline__ void cp_wait() {
    asm volatile("cp.async.wait_group %0;" :: "n"(N) : "memory");
}

// ---------------------------------------------------------------------------
// k_pre: bid < 512  -> streaming f32 -> (bf16 hi, bf16 lo) convert of w
//        bid >= 512 -> one y-row: copy into out + argmax/max
// Both populations are DRAM-bound and independent; they overlap in one wave.
// ---------------------------------------------------------------------------
#define NCONV 512

__global__ void __launch_bounds__(256)
k_pre(const float* __restrict__ w,
      const float* __restrict__ y,
      float* __restrict__ out) {
    const int t = threadIdx.x;

    if (blockIdx.x < NCONV) {
        // flat convert: 128K float4 total; idx -> row = idx>>7, q = idx&127
        const int idx = blockIdx.x * 256 + t;        // < 131072; rows 0..1023
        const int row = idx >> 7;
        if (row >= CC) return;                        // pad rows stay zero
        const int q = idx & 127;
        const float4 v = __ldg((const float4*)(w + (long)row * HH) + q);
        const float e[4] = {v.x, v.y, v.z, v.w};
        uint64_t packhi = 0, packlo = 0;
        #pragma unroll
        for (int i = 0; i < 4; i++) {
            const __nv_bfloat16 h = __float2bfloat16(e[i]);
            const __nv_bfloat16 l = __float2bfloat16(e[i] - __bfloat162float(h));
            packhi |= (uint64_t)__bfloat16_as_ushort(h) << (16 * i);
            packlo |= (uint64_t)__bfloat16_as_ushort(l) << (16 * i);
        }
        *(uint64_t*)&g_whi[(long)row * HH + 4 * q] = packhi;
        *(uint64_t*)&g_wlo[(long)row * HH + 4 * q] = packlo;
        return;
    }

    // ---------------- copy + argmax: one y-row per block ----------------
    __shared__ float sv[8];
    __shared__ int   si[8];
    const int b = blockIdx.x - NCONV;
    const int lane = t & 31, wid = t >> 5;
    const float4* yr = (const float4*)(y + (long)b * CC);
    float* orow = out + (long)b * (CC + 1);

    float vmax = NEG_INF; int imax = 0x7fffffff;
    if (t < CC / 4) {
        const float4 vy = __ldg(&yr[t]);
        const int c = t * 4;
        orow[c] = vy.x; orow[c + 1] = vy.y; orow[c + 2] = vy.z; orow[c + 3] = vy.w;
        vmax = vy.x; imax = c;
        if (vy.y > vmax) { vmax = vy.y; imax = c + 1; }
        if (vy.z > vmax) { vmax = vy.z; imax = c + 2; }
        if (vy.w > vmax) { vmax = vy.w; imax = c + 3; }
    }
    #pragma unroll
    for (int o = 16; o > 0; o >>= 1) {
        const float v2 = __shfl_xor_sync(0xffffffffu, vmax, o);
        const int   i2 = __shfl_xor_sync(0xffffffffu, imax, o);
        if (v2 > vmax || (v2 == vmax && i2 < imax)) { vmax = v2; imax = i2; }
    }
    if (lane == 0) { sv[wid] = vmax; si[wid] = imax; }
    __syncthreads();
    if (t == 0) {
        float bv = sv[0]; int bi = si[0];
        #pragma unroll
        for (int k = 1; k < 8; k++)
            if (sv[k] > bv || (sv[k] == bv && si[k] < bi)) { bv = sv[k]; bi = si[k]; }
        g_ymax[b] = bv; g_jmax[b] = bi;
    }
}

// ---------------------------------------------------------------------------
// k_gram: bf16-split Gram on tensor pipe. 136 CTAs (16x16 upper-tri of 64x64
// tiles), 256 threads (8 warps, warp tile 16x32 -> 2 warps/SMSP hides LDSM).
// G = hi*hi^T + hi*lo^T + lo*hi^T; cp.async double-buffered K-chunks of 32.
// Diagonal tiles also emit g_norm.
// ---------------------------------------------------------------------------
#define NTT 16
#define NPAIR (NTT * (NTT + 1) / 2)   // 136
#define BKC 32
#define NKS (HH / BKC)                // 16
#define SST 40                        // bf16 stride: 80B rows, conflict-free
#define OPBYTES (64 * SST * 2)        // 5120 B per operand buffer

__global__ void __launch_bounds__(256)
k_gram() {
    __shared__ __align__(16) char smem_raw[2 * 4 * OPBYTES];   // 40KB
    float* Cs = (float*)smem_raw;                              // epilogue 64x68

    const int t = threadIdx.x;
    const int warp = t >> 5;
    const int wr = (warp >> 1) * 16;  // 0..48
    const int wc = (warp & 1) * 32;   // 0,32

    int p = blockIdx.x, ti = 0;
    while (p >= NTT - ti) { p -= NTT - ti; ti++; }
    const int tj = ti + p;

    // loader: lrow = t>>2 (0..63), seg = t&3 -> one 16B per operand
    const int lrow = t >> 2;
    const int seg = t & 3;
    const long aoff = (long)(ti * 64 + lrow) * HH + seg * 8;
    const long boff = (long)(tj * 64 + lrow) * HH + seg * 8;
    const uint32_t sdst = smem_u32(smem_raw) + lrow * (SST * 2) + seg * 16;

    const __nv_bfloat16* gsrc[4] = {g_whi, g_wlo, g_whi, g_wlo};

    auto issue = [&](int chunk, int buf) {
        const long co = (long)chunk * BKC;
        #pragma unroll
        for (int op = 0; op < 4; op++) {
            const __nv_bfloat16* src = gsrc[op] + ((op < 2) ? aoff : boff) + co;
            cp16(sdst + (buf * 4 + op) * OPBYTES, src);
        }
    };

    wmma::fragment<wmma::accumulator, 16, 16, 16, float> acc[2];
    wmma::fill_fragment(acc[0], 0.f);
    wmma::fill_fragment(acc[1], 0.f);

    issue(0, 0); cp_commit();
    issue(1, 1); cp_commit();

    #pragma unroll 1
    for (int ks = 0; ks < NKS; ks++) {
        const int buf = ks & 1;
        cp_wait<1>();
        __syncthreads();

        const __nv_bfloat16* sAhi = (const __nv_bfloat16*)(smem_raw + (buf * 4 + 0) * OPBYTES);
        const __nv_bfloat16* sAlo = (const __nv_bfloat16*)(smem_raw + (buf * 4 + 1) * OPBYTES);
        const __nv_bfloat16* sBhi = (const __nv_bfloat16*)(smem_raw + (buf * 4 + 2) * OPBYTES);
        const __nv_bfloat16* sBlo = (const __nv_bfloat16*)(smem_raw + (buf * 4 + 3) * OPBYTES);

        #pragma unroll
        for (int kk = 0; kk < BKC; kk += 16) {
            wmma::fragment<wmma::matrix_a, 16, 16, 16, __nv_bfloat16, wmma::row_major> ah, al;
            wmma::fragment<wmma::matrix_b, 16, 16, 16, __nv_bfloat16, wmma::col_major> bh[2], bl[2];
            wmma::load_matrix_sync(ah, sAhi + wr * SST + kk, SST);
            wmma::load_matrix_sync(al, sAlo + wr * SST + kk, SST);
            #pragma unroll
            for (int j = 0; j < 2; j++) {
                wmma::load_matrix_sync(bh[j], sBhi + (wc + 16 * j) * SST + kk, SST);
                wmma::load_matrix_sync(bl[j], sBlo + (wc + 16 * j) * SST + kk, SST);
            }
            #pragma unroll
            for (int j = 0; j < 2; j++) {
                wmma::mma_sync(acc[j], ah, bh[j], acc[j]);
                wmma::mma_sync(acc[j], ah, bl[j], acc[j]);
                wmma::mma_sync(acc[j], al, bh[j], acc[j]);
            }
        }
        __syncthreads();

        if (ks + 2 < NKS) issue(ks + 2, buf);
        cp_commit();
    }

    cp_wait<0>();
    __syncthreads();   // safe to reuse smem as Cs

    #pragma unroll
    for (int j = 0; j < 2; j++)
        wmma::store_matrix_sync(Cs + wr * 68 + wc + 16 * j, acc[j], 68, wmma::mem_row_major);
    __syncthreads();

    for (int idx = t; idx < 64 * 16; idx += 256) {      // upper tile
        const int r = idx >> 4, c4 = idx & 15;
        const float4 v = *(const float4*)(Cs + r * 68 + c4 * 4);
        *(float4*)&g_G[(long)(ti * 64 + r) * 1024 + tj * 64 + c4 * 4] = v;
    }
    for (int idx = t; idx < 64 * 16; idx += 256) {      // mirror (transposed)
        const int c = idx >> 4, r4 = idx & 15;
        float4 v;
        v.x = Cs[(4 * r4 + 0) * 68 + c];
        v.y = Cs[(4 * r4 + 1) * 68 + c];
        v.z = Cs[(4 * r4 + 2) * 68 + c];
        v.w = Cs[(4 * r4 + 3) * 68 + c];
        *(float4*)&g_G[(long)(tj * 64 + c) * 1024 + ti * 64 + 4 * r4] = v;
    }
    if (ti == tj && t < 64)                             // free norms
        g_norm[ti * 64 + t] = Cs[t * 68 + t];
}

// ---------------------------------------------------------------------------
// k_bot: y_bot only (argmax/copy done in k_pre). 1024 blocks x 256 threads.
// ---------------------------------------------------------------------------
__global__ void __launch_bounds__(256)
k_bot(const float* __restrict__ y,
      const float* __restrict__ eps_p,
      const float* __restrict__ lip_p,
      float* __restrict__ out) {
    const int b = blockIdx.x;
    const int t = threadIdx.x;
    const int lane = t & 31, wid = t >> 5;
    __shared__ float sm[8];

    const float s  = (*eps_p) * fabsf(*lip_p);
    const float s2 = s * s;
    const int   j    = g_jmax[b];
    const float ymax = g_ymax[b];
    const float nj   = g_norm[j];

    float best = NEG_INF;
    if (t < CC / 4) {
        const float4 vy = __ldg((const float4*)(y + (long)b * CC) + t);
        const float4 gv = *((const float4*)(g_G + (long)j * 1024) + t);
        const float4 nv = *((const float4*)g_norm + t);
        const float ye[4] = {vy.x, vy.y, vy.z, vy.w};
        const float ge[4] = {gv.x, gv.y, gv.z, gv.w};
        const float ne[4] = {nv.x, nv.y, nv.z, nv.w};
        #pragma unroll
        for (int e = 0; e < 4; e++) {
            if (ye[e] == ymax) continue;        // ref masks y==ymax -> -inf
            float sq = fmaf(-2.f, ge[e], nj + ne[e]);
            if (sq < 0.f) sq = 0.f;
            const float d = best - ye[e];
            if (d <= 0.f || sq * s2 > d * d)
                best = fmaxf(best, fmaf(s, sqrtf(sq), ye[e]));
        }
    }
    #pragma unroll
    for (int o = 16; o > 0; o >>= 1)
        best = fmaxf(best, __shfl_xor_sync(0xffffffffu, best, o));
    if (lane == 0) sm[wid] = best;
    __syncthreads();
    if (t == 0) {
        float r = sm[0];
        #pragma unroll
        for (int k = 1; k < 8; k++) r = fmaxf(r, sm[k]);
        out[(long)b * (CC + 1) + CC] = r;
    }
}

// ---------------------------------------------------------------------------
extern "C" void kernel_launch(void* const* d_in, const int* in_sizes, int n_in,
                              void* d_out, int out_size) {
    const float* y   = (const float*)d_in[0];
    const float* w   = (const float*)d_in[1];
    const float* eps = (const float*)d_in[2];
    const float* lip = (const float*)d_in[3];
    float* out = (float*)d_out;

    k_pre<<<NCONV + BB, 256>>>(w, y, out);
    k_gram<<<NPAIR, 256>>>();
    k_bot<<<BB, 256>>>(y, eps, lip, out);
}